// round 14
// baseline (speedup 1.0000x reference)
#include <cuda_runtime.h>
#include <math.h>

#define SLEN 8192
#define EDIM 512
#define HH   512
#define G4   2048
#define HD   1024
#define KTAG 5
#define NEGV -10000.0f
#define NCTA 64           /* CTAs per direction */
#define UNITS 8           /* hidden units per CTA */
#define LTHREADS 256
#define VOCAB 50257

// ---------------- scratch (device globals: allocation-free) ----------------
__device__ float g_x[SLEN * EDIM];
__device__ float g_xp[2][SLEN * G4];
__device__ float g_hs[2][SLEN * HH];
__device__ float g_feats[SLEN * KTAG];
// packed h exchange: word = (stamp<<32)|float_bits. [dir][parity][unit]
__device__ __align__(128) unsigned long long g_hpk[2][2][HH];

// ---------------- init: publish h0 with stamp 0; sentinel parity-1 ----------
__global__ void init_kernel(const float* __restrict__ h0) {
    int i = blockIdx.x * 256 + threadIdx.x;              // 0..1023
    int dir = i >> 9, unit = i & 511;
    g_hpk[dir][0][unit] = (unsigned long long)__float_as_uint(h0[i]);
    g_hpk[dir][1][unit] = 0xFFFFFFFF00000000ull;         // matches no step
}

// ---------------- fast gate math (MUFU-based, saturation-safe) ----------------
__device__ __forceinline__ float sigf(float x) {
    return __fdividef(1.f, 1.f + __expf(-x));
}
__device__ __forceinline__ float tanhfast(float x) {
    return 1.f - __fdividef(2.f, __expf(2.f * x) + 1.f);
}

// ---------------- embedding gather ----------------
__global__ void gather_kernel(const int* __restrict__ sent,
                              const float* __restrict__ embed) {
    int t = blockIdx.x;
    unsigned v = (unsigned)sent[t];
    if (v >= (unsigned)VOCAB) v = 0u;
    const float4* src = (const float4*)(embed + (size_t)v * EDIM);
    float4* dst = (float4*)(g_x + (size_t)t * EDIM);
    dst[threadIdx.x] = src[threadIdx.x];
}

// ---------------- input projection GEMM: xp = x @ W_ih^T + b ----------------
#define BM 128
#define BN 128
#define BK 16
__global__ void __launch_bounds__(256)
gemm_kernel(const float* __restrict__ Wf, const float* __restrict__ bf,
            const float* __restrict__ Wb, const float* __restrict__ bb) {
    int dir = blockIdx.z;
    const float* W    = dir ? Wb : Wf;
    const float* bias = dir ? bb : bf;
    float* out = g_xp[dir];

    __shared__ float As[BK][BM + 4];
    __shared__ float Bs[BK][BN + 4];

    int tid = threadIdx.x;
    int m0 = blockIdx.y * BM, n0 = blockIdx.x * BN;
    int tx = tid & 15, ty = tid >> 4;

    float acc[8][8];
#pragma unroll
    for (int i = 0; i < 8; i++)
#pragma unroll
        for (int j = 0; j < 8; j++) acc[i][j] = 0.f;

    const float* Aptr = g_x + (size_t)m0 * EDIM;
    const float* Bptr = W   + (size_t)n0 * EDIM;

    for (int k0 = 0; k0 < EDIM; k0 += BK) {
#pragma unroll
        for (int it = 0; it < 2; it++) {
            int idx = tid + it * 256;
            int row = idx >> 2;
            int kc  = (idx & 3) * 4;
            float4 a = *(const float4*)(Aptr + (size_t)row * EDIM + k0 + kc);
            As[kc + 0][row] = a.x; As[kc + 1][row] = a.y;
            As[kc + 2][row] = a.z; As[kc + 3][row] = a.w;
            float4 b = *(const float4*)(Bptr + (size_t)row * EDIM + k0 + kc);
            Bs[kc + 0][row] = b.x; Bs[kc + 1][row] = b.y;
            Bs[kc + 2][row] = b.z; Bs[kc + 3][row] = b.w;
        }
        __syncthreads();
#pragma unroll
        for (int k = 0; k < BK; k++) {
            float a[8], b[8];
#pragma unroll
            for (int i = 0; i < 8; i++) a[i] = As[k][ty * 8 + i];
#pragma unroll
            for (int j = 0; j < 8; j++) b[j] = Bs[k][tx * 8 + j];
#pragma unroll
            for (int i = 0; i < 8; i++)
#pragma unroll
                for (int j = 0; j < 8; j++) acc[i][j] += a[i] * b[j];
        }
        __syncthreads();
    }
#pragma unroll
    for (int i = 0; i < 8; i++) {
        int m = m0 + ty * 8 + i;
#pragma unroll
        for (int j = 0; j < 8; j++) {
            int n = n0 + tx * 8 + j;
            out[(size_t)m * G4 + n] = acc[i][j] + bias[n];
        }
    }
}

// ---------------- persistent bidirectional LSTM scan ----------------
// 64 CTAs/dir, 8 warps/CTA (warp u <-> unit base+u). Per step t:
//   EACH warp polls its own 64-pack segment (2 ld.relaxed.gpu per lane ->
//   loop period = one L2 RT, vs 16-load chain in R13) and scatters to its
//   hsh segment; one bar. Compute. Each warp's lane0 publishes its pack
//   directly with st.release (stamp t+1) -- no staging smem, no extra bar.
//   Second bar protects hsh rewrite. Safety: pack words are self-consistent
//   8B; overwrite at t+2 is gated through two publish->poll generations.
__global__ void __launch_bounds__(LTHREADS)
lstm_kernel(const float* __restrict__ Whh_f, const float* __restrict__ Whh_b,
            const float* __restrict__ c0) {
    __shared__ float hsh[HH];
    int dir  = blockIdx.x >> 6;
    int cb   = blockIdx.x & 63;
    int base = cb * UNITS;

    const float* Whh = dir ? Whh_b : Whh_f;
    const float* xp  = g_xp[dir];
    float* hs        = g_hs[dir];

    int tid = threadIdx.x, lane = tid & 31, wid = tid >> 5;
    int unit = base + wid;

    float wr[4][16];
#pragma unroll
    for (int g = 0; g < 4; g++) {
        const float* row = Whh + (size_t)(unit + 512 * g) * HH;
#pragma unroll
        for (int k = 0; k < 16; k++) wr[g][k] = row[lane + 32 * k];
    }

    float c = (lane == 0) ? c0[dir * HH + unit] : 0.f;

    // prefetch xp for step 0: lane g<4 holds gate g's xp value for this unit
    float xn = 0.f;
    {
        int tt = dir ? (SLEN - 1) : 0;
        if (lane < 4) xn = xp[(size_t)tt * G4 + unit + 512 * lane];
    }

    int seg = wid * 64 + lane;                  // this thread's 2 poll slots

    for (int t = 0; t < SLEN; t++) {
        // ---- distributed poll: each warp waits on its own 64 packs ----
        {
            const unsigned long long* buf = g_hpk[dir][t & 1];
            unsigned stamp = (unsigned)t;
            unsigned long long v0, v1;
            for (;;) {
                asm volatile("ld.relaxed.gpu.global.b64 %0, [%1];"
                             : "=l"(v0) : "l"(buf + seg) : "memory");
                asm volatile("ld.relaxed.gpu.global.b64 %0, [%1];"
                             : "=l"(v1) : "l"(buf + seg + 32) : "memory");
                if (__all_sync(0xffffffffu,
                               ((unsigned)(v0 >> 32) == stamp) &&
                               ((unsigned)(v1 >> 32) == stamp))) break;
            }
            hsh[seg]      = __uint_as_float((unsigned)v0);
            hsh[seg + 32] = __uint_as_float((unsigned)v1);
        }
        __syncthreads();                       // hsh whole for all warps

        float xv = xn;
        if (t + 1 < SLEN && lane < 4) {
            int tt = dir ? (SLEN - 2 - t) : (t + 1);
            xn = xp[(size_t)tt * G4 + unit + 512 * lane];
        }

        float p0 = 0.f, p1 = 0.f, p2 = 0.f, p3 = 0.f;
#pragma unroll
        for (int k = 0; k < 16; k++) {
            float hv = hsh[lane + 32 * k];     // conflict-free
            p0 += wr[0][k] * hv;
            p1 += wr[1][k] * hv;
            p2 += wr[2][k] * hv;
            p3 += wr[3][k] * hv;
        }
        if      (lane == 0) p0 += xv;
        else if (lane == 1) p1 += xv;
        else if (lane == 2) p2 += xv;
        else if (lane == 3) p3 += xv;
#pragma unroll
        for (int off = 16; off; off >>= 1) {
            p0 += __shfl_down_sync(0xffffffffu, p0, off);
            p1 += __shfl_down_sync(0xffffffffu, p1, off);
            p2 += __shfl_down_sync(0xffffffffu, p2, off);
            p3 += __shfl_down_sync(0xffffffffu, p3, off);
        }

        int tt = dir ? (SLEN - 1 - t) : t;
        if (lane == 0) {
            float ig = sigf(p0);
            float fg = sigf(p1);
            float gg = tanhfast(p2);
            float og = sigf(p3);
            c = fg * c + ig * gg;
            float h = og * tanhfast(c);
            // publish immediately (critical path), then archive
            unsigned long long pk =
                ((unsigned long long)(unsigned)(t + 1) << 32) |
                (unsigned long long)__float_as_uint(h);
            asm volatile("st.release.gpu.global.b64 [%0], %1;"
                         :: "l"(&g_hpk[dir][(t + 1) & 1][unit]), "l"(pk)
                         : "memory");
            hs[(size_t)tt * HH + unit] = h;
        }
        __syncthreads();                       // all hsh reads done before
                                               // next iteration's scatter
    }
}

// ---------------- feats = [hf|hb] @ W_out^T + b_out ----------------
__global__ void __launch_bounds__(256)
feats_kernel(const float* __restrict__ Wout, const float* __restrict__ bout) {
    __shared__ float wsh[KTAG * HD];
    int tid = threadIdx.x;
    for (int i = tid; i < KTAG * HD; i += 256) wsh[i] = Wout[i];
    __syncthreads();

    int lane = tid & 31, wid = tid >> 5;
    int t = blockIdx.x * 8 + wid;
    const float* hf = g_hs[0] + (size_t)t * HH;
    const float* hb = g_hs[1] + (size_t)t * HH;

    float acc[KTAG];
#pragma unroll
    for (int k = 0; k < KTAG; k++) acc[k] = 0.f;
#pragma unroll
    for (int j = 0; j < 8; j++) {
        int d = j * 128 + lane * 4;
        float4 h = (j < 4) ? *(const float4*)(hf + d)
                           : *(const float4*)(hb + d - 512);
#pragma unroll
        for (int k = 0; k < KTAG; k++) {
            float4 wv = *(const float4*)&wsh[k * HD + d];
            acc[k] += h.x * wv.x + h.y * wv.y + h.z * wv.z + h.w * wv.w;
        }
    }
#pragma unroll
    for (int off = 16; off; off >>= 1)
#pragma unroll
        for (int k = 0; k < KTAG; k++)
            acc[k] += __shfl_down_sync(0xffffffffu, acc[k], off);
    if (lane == 0) {
#pragma unroll
        for (int k = 0; k < KTAG; k++)
            g_feats[(size_t)t * KTAG + k] = acc[k] + bout[k];
    }
}

// ---------------- Viterbi decode + backtrace (single CTA) ----------------
#define VCH 256
__global__ void viterbi_kernel(const float* __restrict__ trans,
                               float* __restrict__ out, int out_size) {
    extern __shared__ char vsm[];
    char*  bp = vsm;
    float* fb = (float*)(vsm + SLEN * KTAG);

    int tid = threadIdx.x, lane = tid & 31;
    float Trow[KTAG] = {0, 0, 0, 0, 0};
    float fv = NEGV;
    if (lane < KTAG) {
#pragma unroll
        for (int p = 0; p < KTAG; p++) Trow[p] = trans[lane * KTAG + p];
        fv = (lane == 3) ? 0.f : NEGV;                 // START = 3
    }

    for (int chunk = 0; chunk < SLEN / VCH; chunk++) {
        __syncthreads();
        for (int i = tid; i < VCH * KTAG; i += blockDim.x)
            fb[i] = g_feats[(size_t)chunk * VCH * KTAG + i];
        __syncthreads();
        if (tid < 32) {
            for (int i = 0; i < VCH; i++) {
                int t = chunk * VCH + i;
                float f0 = __shfl_sync(0xffffffffu, fv, 0);
                float f1 = __shfl_sync(0xffffffffu, fv, 1);
                float f2 = __shfl_sync(0xffffffffu, fv, 2);
                float f3 = __shfl_sync(0xffffffffu, fv, 3);
                float f4 = __shfl_sync(0xffffffffu, fv, 4);
                if (lane < KTAG) {
                    float best = f0 + Trow[0]; int arg = 0; float s;
                    s = f1 + Trow[1]; if (s > best) { best = s; arg = 1; }
                    s = f2 + Trow[2]; if (s > best) { best = s; arg = 2; }
                    s = f3 + Trow[3]; if (s > best) { best = s; arg = 3; }
                    s = f4 + Trow[4]; if (s > best) { best = s; arg = 4; }
                    fv = best + fb[i * KTAG + lane];
                    bp[(size_t)t * KTAG + lane] = (char)arg;
                }
            }
        }
    }
    __syncthreads();
    if (tid < 32) {
        float term = NEGV;
        if (lane < KTAG) term = fv + trans[4 * KTAG + lane];   // STOP = 4
        float t0 = __shfl_sync(0xffffffffu, term, 0);
        float t1 = __shfl_sync(0xffffffffu, term, 1);
        float t2 = __shfl_sync(0xffffffffu, term, 2);
        float t3 = __shfl_sync(0xffffffffu, term, 3);
        float t4 = __shfl_sync(0xffffffffu, term, 4);
        if (lane == 0) {
            float best = t0; int bi = 0;
            if (t1 > best) { best = t1; bi = 1; }
            if (t2 > best) { best = t2; bi = 2; }
            if (t3 > best) { best = t3; bi = 3; }
            if (t4 > best) { best = t4; bi = 4; }
            out[0] = best;
            int tag = bi;
            for (int t = SLEN - 1; t >= 0; t--) {
                if (1 + t < out_size) out[1 + t] = (float)tag;
                tag = (int)bp[(size_t)t * KTAG + tag];
            }
        }
    }
}

// ---------------- launch: positional binding (dict order) ----------------
extern "C" void kernel_launch(void* const* d_in, const int* in_sizes, int n_in,
                              void* d_out, int out_size) {
    const int*   sent  = (const int*)d_in[0];
    const float* embed = (const float*)d_in[1];
    const float* Wih_f = (const float*)d_in[2];
    const float* Whh_f = (const float*)d_in[3];
    const float* b_f   = (const float*)d_in[4];
    const float* Wih_b = (const float*)d_in[5];
    const float* Whh_b = (const float*)d_in[6];
    const float* b_b   = (const float*)d_in[7];
    const float* Wout  = (const float*)d_in[8];
    const float* bout  = (const float*)d_in[9];
    const float* trans = (const float*)d_in[10];
    const float* h0    = (const float*)d_in[11];
    const float* c0    = (const float*)d_in[12];
    float* out = (float*)d_out;

    init_kernel<<<4, 256>>>(h0);
    gather_kernel<<<SLEN, EDIM / 4>>>(sent, embed);
    dim3 gg(G4 / BN, SLEN / BM, 2);
    gemm_kernel<<<gg, 256>>>(Wih_f, b_f, Wih_b, b_b);
    lstm_kernel<<<128, LTHREADS>>>(Whh_f, Whh_b, c0);
    feats_kernel<<<SLEN / 8, 256>>>(Wout, bout);
    viterbi_kernel<<<1, 256, SLEN * KTAG + VCH * KTAG * 4>>>(trans, out, out_size);
}

// round 15
// speedup vs baseline: 1.3037x; 1.3037x over previous
#include <cuda_runtime.h>
#include <math.h>

#define SLEN 8192
#define EDIM 512
#define HH   512
#define G4   2048
#define HD   1024
#define KTAG 5
#define NEGV -10000.0f
#define NCTA 64           /* LSTM CTAs per direction */
#define UNITS 8
#define VOCAB 50257

#define BM 128
#define BN 128
#define BK 16
#define NTILES 16         /* G4 / BN */
#define MTILES 64         /* SLEN / BM */
#define GEMM_CTAS (NTILES * 2 * MTILES)
#define FUSED_CTAS (128 + GEMM_CTAS)

// ---------------- scratch (device globals: allocation-free) ----------------
__device__ float g_xp[2][SLEN * G4];
__device__ float g_hs[2][SLEN * HH];
__device__ float g_feats[SLEN * KTAG];
// packed h exchange: word = (stamp<<32)|float_bits. [dir][parity][unit]
__device__ __align__(128) unsigned long long g_hpk[2][2][HH];
// xp tile readiness counters, indexed by CONSUMPTION order z (0..63) per dir
__device__ unsigned g_xpflag[2][MTILES];

// ---------------- init: h0 packs, sentinel, zero tile flags ----------------
__global__ void init_kernel(const float* __restrict__ h0) {
    int i = blockIdx.x * 256 + threadIdx.x;              // 0..1023
    if (i < 2 * MTILES) ((unsigned*)g_xpflag)[i] = 0u;
    int dir = i >> 9, unit = i & 511;
    g_hpk[dir][0][unit] = (unsigned long long)__float_as_uint(h0[i]);
    g_hpk[dir][1][unit] = 0xFFFFFFFF00000000ull;         // matches no step
}

// ---------------- fast gate math (MUFU-based, saturation-safe) ----------------
__device__ __forceinline__ float sigf(float x) {
    return __fdividef(1.f, 1.f + __expf(-x));
}
__device__ __forceinline__ float tanhfast(float x) {
    return 1.f - __fdividef(2.f, __expf(2.f * x) + 1.f);
}

// =====================================================================
// FUSED kernel: blocks 0..127 = persistent LSTM (R13 protocol frozen);
// blocks 128..  = GEMM xp tiles (gather fused) publishing tile flags.
// =====================================================================
__global__ void __launch_bounds__(256, 2)
fused_kernel(const int* __restrict__ sent, const float* __restrict__ embed,
             const float* __restrict__ Wih_f, const float* __restrict__ b_f,
             const float* __restrict__ Wih_b, const float* __restrict__ b_b,
             const float* __restrict__ Whh_f, const float* __restrict__ Whh_b,
             const float* __restrict__ c0) {
    __shared__ float spool[2 * BK * (BM + 4)];           // 16.9 KB union
    int tid = threadIdx.x;

    if (blockIdx.x >= 128) {
        // ---------------- GEMM role: xp = x @ W_ih^T + b ----------------
        int g     = blockIdx.x - 128;
        int nt    = g % NTILES;                  // N tile
        int dirg  = (g / NTILES) & 1;
        int zz    = g / (NTILES * 2);            // consumption-order index
        int mtile = dirg ? (MTILES - 1 - zz) : zz;
        int m0 = mtile * BM, n0 = nt * BN;

        const float* W    = dirg ? Wih_b : Wih_f;
        const float* bias = dirg ? b_b : b_f;
        float* out = g_xp[dirg];

        float (*As)[BM + 4] = (float(*)[BM + 4])spool;
        float (*Bs)[BN + 4] = (float(*)[BN + 4])(spool + BK * (BM + 4));

        int tx = tid & 15, ty = tid >> 4;
        float acc[8][8];
#pragma unroll
        for (int i = 0; i < 8; i++)
#pragma unroll
            for (int j = 0; j < 8; j++) acc[i][j] = 0.f;

        // fused gather: each thread owns rows tid>>2 and (tid+256)>>2
        unsigned tok0, tok1;
        {
            unsigned v0 = (unsigned)sent[m0 + (tid >> 2)];
            unsigned v1 = (unsigned)sent[m0 + ((tid + 256) >> 2)];
            tok0 = v0 < (unsigned)VOCAB ? v0 : 0u;
            tok1 = v1 < (unsigned)VOCAB ? v1 : 0u;
        }
        const float* Bptr = W + (size_t)n0 * EDIM;

        for (int k0 = 0; k0 < EDIM; k0 += BK) {
#pragma unroll
            for (int it = 0; it < 2; it++) {
                int idx = tid + it * 256;
                int row = idx >> 2;
                int kc  = (idx & 3) * 4;
                unsigned tok = it ? tok1 : tok0;
                float4 a = *(const float4*)(embed + (size_t)tok * EDIM + k0 + kc);
                As[kc + 0][row] = a.x; As[kc + 1][row] = a.y;
                As[kc + 2][row] = a.z; As[kc + 3][row] = a.w;
                float4 b = *(const float4*)(Bptr + (size_t)row * EDIM + k0 + kc);
                Bs[kc + 0][row] = b.x; Bs[kc + 1][row] = b.y;
                Bs[kc + 2][row] = b.z; Bs[kc + 3][row] = b.w;
            }
            __syncthreads();
#pragma unroll
            for (int k = 0; k < BK; k++) {
                float a[8], b[8];
#pragma unroll
                for (int i = 0; i < 8; i++) a[i] = As[k][ty * 8 + i];
#pragma unroll
                for (int j = 0; j < 8; j++) b[j] = Bs[k][tx * 8 + j];
#pragma unroll
                for (int i = 0; i < 8; i++)
#pragma unroll
                    for (int j = 0; j < 8; j++) acc[i][j] += a[i] * b[j];
            }
            __syncthreads();
        }
#pragma unroll
        for (int i = 0; i < 8; i++) {
            int m = m0 + ty * 8 + i;
#pragma unroll
            for (int j = 0; j < 8; j++) {
                int n = n0 + tx * 8 + j;
                out[(size_t)m * G4 + n] = acc[i][j] + bias[n];
            }
        }
        __syncthreads();                          // all stores issued
        if (tid == 0) {                           // publish tile progress
            unsigned one = 1u;
            asm volatile("red.release.gpu.global.add.u32 [%0], %1;"
                         :: "l"(&g_xpflag[dirg][zz]), "r"(one) : "memory");
        }
        return;
    }

    // ---------------- LSTM role (R13 protocol, + xp tile gating) ----------------
    float* hsh = spool;                           // 512 floats
    float* h8s = spool + HH;                      // 8 floats
    int dir  = blockIdx.x >> 6;
    int cb   = blockIdx.x & 63;
    int base = cb * UNITS;

    const float* Whh = dir ? Whh_b : Whh_f;
    const float* xp  = g_xp[dir];
    float* hs        = g_hs[dir];

    int lane = tid & 31, wid = tid >> 5;
    int unit = base + wid;

    float wr[4][16];
#pragma unroll
    for (int g2 = 0; g2 < 4; g2++) {
        const float* row = Whh + (size_t)(unit + 512 * g2) * HH;
#pragma unroll
        for (int k = 0; k < 16; k++) wr[g2][k] = row[lane + 32 * k];
    }

    float c = (lane == 0) ? c0[dir * HH + unit] : 0.f;

    // initial prefetch (consumption-order tile 0 for both dirs)
    float xn = 0.f;
    if (lane < 4) {
        const unsigned* fp = &g_xpflag[dir][0];
        unsigned v;
        do {
            asm volatile("ld.acquire.gpu.global.u32 %0, [%1];"
                         : "=r"(v) : "l"(fp) : "memory");
        } while (v < (unsigned)NTILES);
        int tt = dir ? (SLEN - 1) : 0;
        xn = xp[(size_t)tt * G4 + unit + 512 * lane];
    }

    for (int t = 0; t < SLEN; t++) {
        // ---- one-hop acquire: warp0 polls packed words (stamp == t) ----
        if (wid == 0) {
            const unsigned long long* buf = g_hpk[dir][t & 1];
            unsigned stamp = (unsigned)t;
            unsigned hlo[16];
            for (;;) {
                int ok = 1;
#pragma unroll
                for (int k = 0; k < 16; k++) {
                    unsigned long long v;
                    asm volatile("ld.relaxed.gpu.global.b64 %0, [%1];"
                                 : "=l"(v)
                                 : "l"(buf + lane + 32 * k) : "memory");
                    hlo[k] = (unsigned)v;
                    ok &= ((unsigned)(v >> 32) == stamp);
                }
                if (__all_sync(0xffffffffu, ok)) break;
            }
#pragma unroll
            for (int k = 0; k < 16; k++)
                hsh[lane + 32 * k] = __uint_as_float(hlo[k]);  // conflict-free
        }
        __syncthreads();                       // hsh ready for all warps

        float xv = xn;
        if (t + 1 < SLEN && lane < 4) {
            if (((t + 1) & 127) == 0) {        // new tile: gate on readiness
                const unsigned* fp = &g_xpflag[dir][(t + 1) >> 7];
                unsigned v;
                do {
                    asm volatile("ld.acquire.gpu.global.u32 %0, [%1];"
                                 : "=r"(v) : "l"(fp) : "memory");
                } while (v < (unsigned)NTILES);
            }
            int tt = dir ? (SLEN - 2 - t) : (t + 1);
            xn = xp[(size_t)tt * G4 + unit + 512 * lane];
        }

        float p0 = 0.f, p1 = 0.f, p2 = 0.f, p3 = 0.f;
#pragma unroll
        for (int k = 0; k < 16; k++) {
            float hv = hsh[lane + 32 * k];     // conflict-free
            p0 += wr[0][k] * hv;
            p1 += wr[1][k] * hv;
            p2 += wr[2][k] * hv;
            p3 += wr[3][k] * hv;
        }
        if      (lane == 0) p0 += xv;
        else if (lane == 1) p1 += xv;
        else if (lane == 2) p2 += xv;
        else if (lane == 3) p3 += xv;
#pragma unroll
        for (int off = 16; off; off >>= 1) {
            p0 += __shfl_down_sync(0xffffffffu, p0, off);
            p1 += __shfl_down_sync(0xffffffffu, p1, off);
            p2 += __shfl_down_sync(0xffffffffu, p2, off);
            p3 += __shfl_down_sync(0xffffffffu, p3, off);
        }

        int tt = dir ? (SLEN - 1 - t) : t;
        if (lane == 0) {
            float ig = sigf(p0);
            float fg = sigf(p1);
            float gg = tanhfast(p2);
            float og = sigf(p3);
            c = fg * c + ig * gg;
            float h = og * tanhfast(c);
            hs[(size_t)tt * HH + unit] = h;
            h8s[wid] = h;
        }
        __syncthreads();                       // h8s ready; hsh reads done
        if (wid == 0 && lane < UNITS) {        // publish 8 packs = one 64B line
            unsigned long long pk =
                ((unsigned long long)(unsigned)(t + 1) << 32) |
                (unsigned long long)__float_as_uint(h8s[lane]);
            asm volatile("st.release.gpu.global.b64 [%0], %1;"
                         :: "l"(&g_hpk[dir][(t + 1) & 1][base + lane]), "l"(pk)
                         : "memory");
        }
        // next iteration's poll + bar protects hsh rewrite
    }
}

// ---------------- feats = [hf|hb] @ W_out^T + b_out ----------------
__global__ void __launch_bounds__(256)
feats_kernel(const float* __restrict__ Wout, const float* __restrict__ bout) {
    __shared__ float wsh[KTAG * HD];
    int tid = threadIdx.x;
    for (int i = tid; i < KTAG * HD; i += 256) wsh[i] = Wout[i];
    __syncthreads();

    int lane = tid & 31, wid = tid >> 5;
    int t = blockIdx.x * 8 + wid;
    const float* hf = g_hs[0] + (size_t)t * HH;
    const float* hb = g_hs[1] + (size_t)t * HH;

    float acc[KTAG];
#pragma unroll
    for (int k = 0; k < KTAG; k++) acc[k] = 0.f;
#pragma unroll
    for (int j = 0; j < 8; j++) {
        int d = j * 128 + lane * 4;
        float4 h = (j < 4) ? *(const float4*)(hf + d)
                           : *(const float4*)(hb + d - 512);
#pragma unroll
        for (int k = 0; k < KTAG; k++) {
            float4 wv = *(const float4*)&wsh[k * HD + d];
            acc[k] += h.x * wv.x + h.y * wv.y + h.z * wv.z + h.w * wv.w;
        }
    }
#pragma unroll
    for (int off = 16; off; off >>= 1)
#pragma unroll
        for (int k = 0; k < KTAG; k++)
            acc[k] += __shfl_down_sync(0xffffffffu, acc[k], off);
    if (lane == 0) {
#pragma unroll
        for (int k = 0; k < KTAG; k++)
            g_feats[(size_t)t * KTAG + k] = acc[k] + bout[k];
    }
}

// ---------------- Viterbi decode + backtrace (single CTA) ----------------
#define VCH 256
__global__ void viterbi_kernel(const float* __restrict__ trans,
                               float* __restrict__ out, int out_size) {
    extern __shared__ char vsm[];
    char*  bp = vsm;
    float* fb = (float*)(vsm + SLEN * KTAG);

    int tid = threadIdx.x, lane = tid & 31;
    float Trow[KTAG] = {0, 0, 0, 0, 0};
    float fv = NEGV;
    if (lane < KTAG) {
#pragma unroll
        for (int p = 0; p < KTAG; p++) Trow[p] = trans[lane * KTAG + p];
        fv = (lane == 3) ? 0.f : NEGV;                 // START = 3
    }

    for (int chunk = 0; chunk < SLEN / VCH; chunk++) {
        __syncthreads();
        for (int i = tid; i < VCH * KTAG; i += blockDim.x)
            fb[i] = g_feats[(size_t)chunk * VCH * KTAG + i];
        __syncthreads();
        if (tid < 32) {
            for (int i = 0; i < VCH; i++) {
                int t = chunk * VCH + i;
                float f0 = __shfl_sync(0xffffffffu, fv, 0);
                float f1 = __shfl_sync(0xffffffffu, fv, 1);
                float f2 = __shfl_sync(0xffffffffu, fv, 2);
                float f3 = __shfl_sync(0xffffffffu, fv, 3);
                float f4 = __shfl_sync(0xffffffffu, fv, 4);
                if (lane < KTAG) {
                    float best = f0 + Trow[0]; int arg = 0; float s;
                    s = f1 + Trow[1]; if (s > best) { best = s; arg = 1; }
                    s = f2 + Trow[2]; if (s > best) { best = s; arg = 2; }
                    s = f3 + Trow[3]; if (s > best) { best = s; arg = 3; }
                    s = f4 + Trow[4]; if (s > best) { best = s; arg = 4; }
                    fv = best + fb[i * KTAG + lane];
                    bp[(size_t)t * KTAG + lane] = (char)arg;
                }
            }
        }
    }
    __syncthreads();
    if (tid < 32) {
        float term = NEGV;
        if (lane < KTAG) term = fv + trans[4 * KTAG + lane];   // STOP = 4
        float t0 = __shfl_sync(0xffffffffu, term, 0);
        float t1 = __shfl_sync(0xffffffffu, term, 1);
        float t2 = __shfl_sync(0xffffffffu, term, 2);
        float t3 = __shfl_sync(0xffffffffu, term, 3);
        float t4 = __shfl_sync(0xffffffffu, term, 4);
        if (lane == 0) {
            float best = t0; int bi = 0;
            if (t1 > best) { best = t1; bi = 1; }
            if (t2 > best) { best = t2; bi = 2; }
            if (t3 > best) { best = t3; bi = 3; }
            if (t4 > best) { best = t4; bi = 4; }
            out[0] = best;
            int tag = bi;
            for (int t = SLEN - 1; t >= 0; t--) {
                if (1 + t < out_size) out[1 + t] = (float)tag;
                tag = (int)bp[(size_t)t * KTAG + tag];
            }
        }
    }
}

// ---------------- launch: positional binding (dict order) ----------------
extern "C" void kernel_launch(void* const* d_in, const int* in_sizes, int n_in,
                              void* d_out, int out_size) {
    const int*   sent  = (const int*)d_in[0];
    const float* embed = (const float*)d_in[1];
    const float* Wih_f = (const float*)d_in[2];
    const float* Whh_f = (const float*)d_in[3];
    const float* b_f   = (const float*)d_in[4];
    const float* Wih_b = (const float*)d_in[5];
    const float* Whh_b = (const float*)d_in[6];
    const float* b_b   = (const float*)d_in[7];
    const float* Wout  = (const float*)d_in[8];
    const float* bout  = (const float*)d_in[9];
    const float* trans = (const float*)d_in[10];
    const float* h0    = (const float*)d_in[11];
    const float* c0    = (const float*)d_in[12];
    float* out = (float*)d_out;

    init_kernel<<<4, 256>>>(h0);
    fused_kernel<<<FUSED_CTAS, 256>>>(sent, embed, Wih_f, b_f, Wih_b, b_b,
                                      Whh_f, Whh_b, c0);
    feats_kernel<<<SLEN / 8, 256>>>(Wout, bout);
    viterbi_kernel<<<1, 256, SLEN * KTAG + VCH * KTAG * 4>>>(trans, out, out_size);
}